// round 1
// baseline (speedup 1.0000x reference)
#include <cuda_runtime.h>

#define NAGENTS 8192
#define OBSLEN  20
#define PREDLEN 30
#define EMBED   64
#define HIDDEN  128
#define CNNOUT  2048
#define GATES   512   /* 4*HIDDEN */
#define KDIM    192   /* EMBED + HIDDEN */

// Scratch (device globals; no allocation allowed)
__device__ float g_Wt[KDIM * GATES];     // transposed combined weights: [k][j]
__device__ float g_bias[GATES];          // b_ih + b_hh
__device__ float g_imgproj[NAGENTS * 2]; // img_embedding @ pred_W[:,128:].T

// ---------------------------------------------------------------------------
// Prep 1: build Wt[k][j] = (k<64 ? W_ih[j][k] : W_hh[j][k-64]), combined bias
// ---------------------------------------------------------------------------
__global__ void prep_weights(const float* __restrict__ W_ih,
                             const float* __restrict__ W_hh,
                             const float* __restrict__ b_ih,
                             const float* __restrict__ b_hh) {
    int idx = blockIdx.x * blockDim.x + threadIdx.x;
    if (idx < KDIM * GATES) {
        int k = idx / GATES, j = idx % GATES;
        g_Wt[idx] = (k < EMBED) ? W_ih[j * EMBED + k] : W_hh[j * HIDDEN + (k - EMBED)];
    }
    if (idx < GATES) g_bias[idx] = b_ih[idx] + b_hh[idx];
}

// ---------------------------------------------------------------------------
// Prep 2: img_proj[n][d] = sum_k img[n][k] * pred_W[d][128+k]   (HBM-bound)
// One warp per agent, float4 loads, shuffle reduce.
// ---------------------------------------------------------------------------
__global__ void img_proj_kernel(const float* __restrict__ img,
                                const float* __restrict__ pred_W) {
    int warp = threadIdx.x >> 5, lane = threadIdx.x & 31;
    int n = blockIdx.x * 8 + warp;
    const float4* ip = (const float4*)(img + (size_t)n * CNNOUT);
    const float4* w0 = (const float4*)(pred_W + HIDDEN);
    const float4* w1 = (const float4*)(pred_W + (HIDDEN + CNNOUT) + HIDDEN);
    float s0 = 0.f, s1 = 0.f;
    for (int i = lane; i < CNNOUT / 4; i += 32) {
        float4 v = ip[i], a = w0[i], b = w1[i];
        s0 += v.x * a.x + v.y * a.y + v.z * a.z + v.w * a.w;
        s1 += v.x * b.x + v.y * b.y + v.z * b.z + v.w * b.w;
    }
#pragma unroll
    for (int o = 16; o; o >>= 1) {
        s0 += __shfl_xor_sync(0xFFFFFFFFu, s0, o);
        s1 += __shfl_xor_sync(0xFFFFFFFFu, s1, o);
    }
    if (lane == 0) { g_imgproj[n * 2] = s0; g_imgproj[n * 2 + 1] = s1; }
}

__device__ __forceinline__ float sigf(float x) { return 1.f / (1.f + __expf(-x)); }

// ---------------------------------------------------------------------------
// Main persistent kernel: 256 threads = 8 warps; 32 agents/block (4/warp).
// Warp w owns agents a0..a0+3; lane l owns gate rows j = jj*32 + l (jj<16),
// so each thread holds i/f/g/o of the same 4 hidden units -> in-register cell.
// h,c live in shared for all 49 steps; weights streamed from L2 each step.
// ---------------------------------------------------------------------------
__global__ __launch_bounds__(256, 2) void lstm_main(
    const float* __restrict__ obs_pos, const int* __restrict__ hist,
    const float* __restrict__ obs_rel, const float* __restrict__ h0,
    const float* __restrict__ embed_W, const float* __restrict__ embed_b,
    const float* __restrict__ pred_W,  const float* __restrict__ pred_b,
    float* __restrict__ out) {
    __shared__ float in_s[KDIM][33];   // rows 0..63: x_emb ; rows 64..191: h (padded 33 vs bank conflicts)
    __shared__ float c_s[HIDDEN][33];
    __shared__ float b_s[GATES];
    __shared__ float ew0_s[EMBED], ew1_s[EMBED], eb_s[EMBED];
    __shared__ float pw_s[2][HIDDEN];
    __shared__ float src_s[32][2];     // rel (obs) or disp (pred)
    __shared__ float pos_s[32][2];
    __shared__ float imgp_s[32][2];
    __shared__ int   hist_s[32];

    int tid  = threadIdx.x;
    int warp = tid >> 5, lane = tid & 31;
    int ab = blockIdx.x * 32;   // agent base
    int a0 = warp * 4;          // this warp's agent group

    // ---- init ----
    for (int i = tid; i < GATES; i += 256) b_s[i] = g_bias[i];
    if (tid < EMBED) {
        ew0_s[tid] = embed_W[tid * 2];
        ew1_s[tid] = embed_W[tid * 2 + 1];
        eb_s[tid]  = embed_b[tid];
    }
    for (int i = tid; i < 2 * HIDDEN; i += 256)
        pw_s[i / HIDDEN][i % HIDDEN] = pred_W[(i / HIDDEN) * (HIDDEN + CNNOUT) + (i % HIDDEN)];
    if (tid < 32) hist_s[tid] = hist[ab + tid];
    if (tid < 64) {
        int a = tid >> 1, d = tid & 1;
        pos_s[a][d]  = obs_pos[(size_t)(ab + a) * OBSLEN * 2 + (OBSLEN - 1) * 2 + d];
        imgp_s[a][d] = g_imgproj[(ab + a) * 2 + d];
    }
    for (int i = tid; i < HIDDEN * 32; i += 256) {
        int k = i >> 5, a = i & 31;
        float hv = h0[k];
        in_s[EMBED + k][a] = hv;
        c_s[k][a] = hv;
    }
    __syncthreads();

    // ---- 49 sequential steps: 19 masked obs + 30 pred ----
    for (int step = 0; step < OBSLEN - 1 + PREDLEN; step++) {
        bool obsPhase = step < OBSLEN - 1;
        int t = obsPhase ? (step + 1) : (step - (OBSLEN - 1)); // obs: 1..19, pred: 0..29

        if (obsPhase) {
            if (tid < 64) {
                int a = tid >> 1, d = tid & 1;
                src_s[a][d] = obs_rel[(size_t)(ab + a) * OBSLEN * 2 + t * 2 + d];
            }
        } else {
            // disp = h @ pred_W[:, :128].T + img_proj + pred_b ; pos += disp
            if (tid < 64) {
                int a = tid >> 1, d = tid & 1;
                float s = 0.f;
#pragma unroll 8
                for (int k = 0; k < HIDDEN; k++) s += pw_s[d][k] * in_s[EMBED + k][a];
                s += imgp_s[a][d] + pred_b[d];
                float p = pos_s[a][d] + s;
                pos_s[a][d] = p;
                out[(size_t)(ab + a) * PREDLEN * 2 + t * 2 + d] = p;
                src_s[a][d] = s;
            }
        }
        __syncthreads();

        // embed: x = relu(src @ embed_W.T + embed_b)
        for (int i = tid; i < EMBED * 32; i += 256) {
            int k = i >> 5, a = i & 31;
            float x = fmaf(ew0_s[k], src_s[a][0], fmaf(ew1_s[k], src_s[a][1], eb_s[k]));
            in_s[k][a] = fmaxf(x, 0.f);
        }
        __syncthreads();

        // gate GEMM: acc[jj][aa] = bias + sum_k Wt[k][jj*32+lane] * in[k][a0+aa]
        float acc[16][4];
#pragma unroll
        for (int jj = 0; jj < 16; jj++) {
            float bv = b_s[jj * 32 + lane];
            acc[jj][0] = bv; acc[jj][1] = bv; acc[jj][2] = bv; acc[jj][3] = bv;
        }
        const float* wp = g_Wt + lane;
        for (int k = 0; k < KDIM; k++) {
            float in0 = in_s[k][a0], in1 = in_s[k][a0 + 1];
            float in2 = in_s[k][a0 + 2], in3 = in_s[k][a0 + 3];
#pragma unroll
            for (int jj = 0; jj < 16; jj++) {
                float w = wp[k * GATES + jj * 32];
                acc[jj][0] = fmaf(w, in0, acc[jj][0]);
                acc[jj][1] = fmaf(w, in1, acc[jj][1]);
                acc[jj][2] = fmaf(w, in2, acc[jj][2]);
                acc[jj][3] = fmaf(w, in3, acc[jj][3]);
            }
        }

        // cell update fully in registers: k = lane + 32*m; gates at jj = m, 4+m, 8+m, 12+m
        bool upd[4];
#pragma unroll
        for (int aa = 0; aa < 4; aa++)
            upd[aa] = obsPhase ? (hist_s[a0 + aa] > OBSLEN - t) : true;
#pragma unroll
        for (int m = 0; m < 4; m++) {
            int k = lane + 32 * m;
#pragma unroll
            for (int aa = 0; aa < 4; aa++) {
                if (upd[aa]) {
                    float iv = acc[m][aa],     fv = acc[4 + m][aa];
                    float gv = acc[8 + m][aa], ov = acc[12 + m][aa];
                    float cold = c_s[k][a0 + aa];
                    float c2 = sigf(fv) * cold + sigf(iv) * tanhf(gv);
                    float h2 = sigf(ov) * tanhf(c2);
                    c_s[k][a0 + aa] = c2;
                    in_s[EMBED + k][a0 + aa] = h2;
                }
            }
        }
        __syncthreads();  // h/c visible to next step's cross-warp readers
    }
}

// ---------------------------------------------------------------------------
extern "C" void kernel_launch(void* const* d_in, const int* in_sizes, int n_in,
                              void* d_out, int out_size) {
    const float* img     = (const float*)d_in[0];
    const float* obs_pos = (const float*)d_in[1];
    const int*   hist    = (const int*)d_in[2];
    const float* obs_rel = (const float*)d_in[3];
    const float* h0      = (const float*)d_in[4];
    const float* W_ih    = (const float*)d_in[5];
    const float* W_hh    = (const float*)d_in[6];
    const float* b_ih    = (const float*)d_in[7];
    const float* b_hh    = (const float*)d_in[8];
    const float* embed_W = (const float*)d_in[9];
    const float* embed_b = (const float*)d_in[10];
    const float* pred_W  = (const float*)d_in[11];
    const float* pred_b  = (const float*)d_in[12];
    float* out = (float*)d_out;

    prep_weights<<<(KDIM * GATES + 255) / 256, 256>>>(W_ih, W_hh, b_ih, b_hh);
    img_proj_kernel<<<NAGENTS / 8, 256>>>(img, pred_W);
    lstm_main<<<NAGENTS / 32, 256>>>(obs_pos, hist, obs_rel, h0,
                                     embed_W, embed_b, pred_W, pred_b, out);
}

// round 3
// speedup vs baseline: 1.2790x; 1.2790x over previous
#include <cuda_runtime.h>

#define NAGENTS 8192
#define OBSLEN  20
#define PREDLEN 30
#define EMBED   64
#define HIDDEN  128
#define CNNOUT  2048
#define GATES   512   /* 4*HIDDEN */
#define KDIM    192   /* EMBED + HIDDEN */

// Weights as f32x2-pair-friendly layout: float index ((k*4+q)*32+lane)*4 + e,
// where jj = 4q+e, gate j = jj*32+lane. One extra zero k-row for prefetch OOB.
__device__ ulonglong2 g_W4[(KDIM + 1) * 4 * 32];
__device__ float g_bias[GATES];
__device__ float g_imgproj[NAGENTS * 2];

__global__ void prep_weights(const float* __restrict__ W_ih,
                             const float* __restrict__ W_hh,
                             const float* __restrict__ b_ih,
                             const float* __restrict__ b_hh) {
    int idx = blockIdx.x * blockDim.x + threadIdx.x;
    if (idx < KDIM * GATES) {
        int k = idx / GATES, j = idx % GATES;
        int lane = j & 31, jj = j >> 5, q = jj >> 2, e = jj & 3;
        float v = (k < EMBED) ? W_ih[j * EMBED + k] : W_hh[j * HIDDEN + (k - EMBED)];
        ((float*)g_W4)[(((k * 4 + q) * 32 + lane) << 2) + e] = v;
    }
    if (idx < GATES) g_bias[idx] = b_ih[idx] + b_hh[idx];
}

__global__ void img_proj_kernel(const float* __restrict__ img,
                                const float* __restrict__ pred_W) {
    int warp = threadIdx.x >> 5, lane = threadIdx.x & 31;
    int n = blockIdx.x * 8 + warp;
    const float4* ip = (const float4*)(img + (size_t)n * CNNOUT);
    const float4* w0 = (const float4*)(pred_W + HIDDEN);
    const float4* w1 = (const float4*)(pred_W + (HIDDEN + CNNOUT) + HIDDEN);
    float s0 = 0.f, s1 = 0.f;
    for (int i = lane; i < CNNOUT / 4; i += 32) {
        float4 v = ip[i], a = w0[i], b = w1[i];
        s0 += v.x * a.x + v.y * a.y + v.z * a.z + v.w * a.w;
        s1 += v.x * b.x + v.y * b.y + v.z * b.z + v.w * b.w;
    }
#pragma unroll
    for (int o = 16; o; o >>= 1) {
        s0 += __shfl_xor_sync(0xFFFFFFFFu, s0, o);
        s1 += __shfl_xor_sync(0xFFFFFFFFu, s1, o);
    }
    if (lane == 0) { g_imgproj[n * 2] = s0; g_imgproj[n * 2 + 1] = s1; }
}

__device__ __forceinline__ float sigf(float x) { return 1.f / (1.f + __expf(-x)); }

__device__ __forceinline__ unsigned long long pack2(float lo, float hi) {
    unsigned long long r;
    asm("mov.b64 %0, {%1, %2};" : "=l"(r) : "f"(lo), "f"(hi));
    return r;
}
__device__ __forceinline__ float2 unpk(unsigned long long v) {
    float2 r;
    asm("mov.b64 {%0, %1}, %2;" : "=f"(r.x), "=f"(r.y) : "l"(v));
    return r;
}
#define FF2(a, w, i) asm("fma.rn.f32x2 %0, %1, %2, %0;" : "+l"(a) : "l"(w), "l"(i))

#define DUPF4 (8 * 2 * 192)
#define SMEM_BYTES ((DUPF4 * 4 + 512 + 64 * 3 + 256 + 64 * 3 + 32) * 4)

// 256 threads = 8 warps, 4 agents/warp, 32 agents/block, grid 256, occ 2.
// Fully warp-local stepping: no __syncthreads in the 49-step loop.
__global__ __launch_bounds__(256, 2) void lstm_main(
    const float* __restrict__ obs_pos, const int* __restrict__ hist,
    const float* __restrict__ obs_rel, const float* __restrict__ h0,
    const float* __restrict__ embed_W, const float* __restrict__ embed_b,
    const float* __restrict__ pred_W,  const float* __restrict__ pred_b,
    float* __restrict__ out) {
    extern __shared__ float4 sm4[];
    float4 (*dup)[2][192] = reinterpret_cast<float4(*)[2][192]>(sm4);  // [warp][pair][k] = (v,v,v',v')
    float* fb = reinterpret_cast<float*>(sm4 + DUPF4);
    unsigned long long* b2_s = (unsigned long long*)fb;   // [8 pairs][32 lanes]
    float* ew0 = fb + 512;
    float* ew1 = ew0 + 64;
    float* eb  = ew1 + 64;
    float* pw  = eb + 64;                                  // [2][128]
    float (*src_s)[2]  = (float(*)[2])(pw + 256);          // [32][2]
    float (*pos_s)[2]  = (float(*)[2])(pw + 256 + 64);
    float (*imgp_s)[2] = (float(*)[2])(pw + 256 + 128);
    int*   hist_s      = (int*)(pw + 256 + 192);

    int tid = threadIdx.x, warp = tid >> 5, lane = tid & 31;
    int ab = blockIdx.x * 32;      // block agent base
    int a0 = warp * 4;             // warp's local agent base

    // ---------------- init (one __syncthreads total) ----------------
    {
        int p = tid >> 5, l = tid & 31;
        b2_s[tid] = pack2(g_bias[p * 64 + l], g_bias[p * 64 + 32 + l]);
    }
    if (tid < 64) {
        ew0[tid] = embed_W[tid * 2];
        ew1[tid] = embed_W[tid * 2 + 1];
        eb[tid]  = embed_b[tid];
    }
    for (int i = tid; i < 256; i += 256)
        pw[i] = pred_W[(i >> 7) * (HIDDEN + CNNOUT) + (i & 127)];
    if (tid < 32) hist_s[tid] = hist[ab + tid];
    if (tid < 64) {
        int a = tid >> 1, d = tid & 1;
        pos_s[a][d]  = obs_pos[(size_t)(ab + a) * OBSLEN * 2 + (OBSLEN - 1) * 2 + d];
        imgp_s[a][d] = g_imgproj[(ab + a) * 2 + d];
    }
    for (int idx = tid; idx < DUPF4; idx += 256) {
        int kk = idx % 192;
        float v = (kk < EMBED) ? 0.f : h0[kk - EMBED];
        ((float4*)sm4)[idx] = make_float4(v, v, v, v);
    }
    float c[4][4];
#pragma unroll
    for (int m = 0; m < 4; m++) {
        float hv = h0[lane + 32 * m];
#pragma unroll
        for (int aa = 0; aa < 4; aa++) c[m][aa] = hv;
    }
    float pbd = pred_b[(lane >> 2) & 1];
    __syncthreads();

    int maxh4 = max(max(hist_s[a0], hist_s[a0 + 1]), max(hist_s[a0 + 2], hist_s[a0 + 3]));

    const ulonglong2* dupA = (const ulonglong2*)&dup[warp][0][0];
    const ulonglong2* dupB = (const ulonglong2*)&dup[warp][1][0];
    const ulonglong2* gW2  = g_W4;

    // ---------------- 49 sequential warp-local steps ----------------
    for (int step = 0; step < OBSLEN - 1 + PREDLEN; step++) {
        bool obsPhase = step < OBSLEN - 1;
        int t = obsPhase ? (step + 1) : (step - (OBSLEN - 1));

        if (obsPhase) {
            if (maxh4 <= OBSLEN - t) continue;   // whole warp masked: h/c unchanged
            if (lane < 8) {
                int a = lane >> 1, d = lane & 1;
                src_s[a0 + a][d] = obs_rel[(size_t)(ab + a0 + a) * OBSLEN * 2 + t * 2 + d];
            }
            __syncwarp();
        } else {
            // disp = h @ pred_W[:, :128].T + img_proj + pred_b; 4 lanes per (agent,dim)
            int pr = lane >> 2, sub = lane & 3;
            int aa = pr >> 1, d = pr & 1;
            const float* hb = (const float*)&dup[warp][aa >> 1][EMBED];
            int comp = (aa & 1) * 2;
            float s = 0.f;
#pragma unroll 8
            for (int kk = 0; kk < 32; kk++) {
                int k = sub + 4 * kk;
                s = fmaf(pw[d * 128 + k], hb[k * 4 + comp], s);
            }
            s += __shfl_xor_sync(0xFFFFFFFFu, s, 1);
            s += __shfl_xor_sync(0xFFFFFFFFu, s, 2);
            if (sub == 0) {
                s += imgp_s[a0 + aa][d] + pbd;
                float p = pos_s[a0 + aa][d] + s;
                pos_s[a0 + aa][d] = p;
                out[(size_t)(ab + a0 + aa) * PREDLEN * 2 + t * 2 + d] = p;
                src_s[a0 + aa][d] = s;
            }
            __syncwarp();
        }

        // embed: x = relu(src @ embed_W.T + embed_b); write duplicated pairs
#pragma unroll
        for (int mm = 0; mm < 2; mm++) {
            int k = lane + mm * 32;
            float w0 = ew0[k], w1 = ew1[k], bb = eb[k];
            float x0 = fmaxf(fmaf(w0, src_s[a0][0],     fmaf(w1, src_s[a0][1],     bb)), 0.f);
            float x1 = fmaxf(fmaf(w0, src_s[a0 + 1][0], fmaf(w1, src_s[a0 + 1][1], bb)), 0.f);
            float x2 = fmaxf(fmaf(w0, src_s[a0 + 2][0], fmaf(w1, src_s[a0 + 2][1], bb)), 0.f);
            float x3 = fmaxf(fmaf(w0, src_s[a0 + 3][0], fmaf(w1, src_s[a0 + 3][1], bb)), 0.f);
            dup[warp][0][k] = make_float4(x0, x0, x1, x1);
            dup[warp][1][k] = make_float4(x2, x2, x3, x3);
        }
        __syncwarp();

        // ---- gate GEMM, f32x2: acc[p][aa] = (gate 2p, gate 2p+1) for agent aa ----
        unsigned long long acc[8][4];
#pragma unroll
        for (int p = 0; p < 8; p++) {
            unsigned long long b = b2_s[p * 32 + lane];
            acc[p][0] = b; acc[p][1] = b; acc[p][2] = b; acc[p][3] = b;
        }
        const ulonglong2* wk = gW2 + lane;
        ulonglong2 wA = wk[0], wB = wk[32], wC = wk[64], wD = wk[96];
#pragma unroll 1
        for (int k = 0; k < KDIM; k++) {
            const ulonglong2* nw = wk + 128;           // next k (extra zero row pads OOB)
            ulonglong2 nA = nw[0], nB = nw[32], nC = nw[64], nD = nw[96];
            ulonglong2 dA = dupA[k], dB = dupB[k];
#define FMA4(p, w) FF2(acc[p][0], w, dA.x); FF2(acc[p][1], w, dA.y); \
                   FF2(acc[p][2], w, dB.x); FF2(acc[p][3], w, dB.y)
            FMA4(0, wA.x); FMA4(1, wA.y); FMA4(2, wB.x); FMA4(3, wB.y);
            FMA4(4, wC.x); FMA4(5, wC.y); FMA4(6, wD.x); FMA4(7, wD.y);
#undef FMA4
            wA = nA; wB = nB; wC = nC; wD = nD;
            wk = nw;
        }

        // ---- cell update (c in regs); h written back duplicated ----
        bool upd[4];
#pragma unroll
        for (int aa = 0; aa < 4; aa++)
            upd[aa] = !obsPhase || (hist_s[a0 + aa] > OBSLEN - t);
#pragma unroll
        for (int m = 0; m < 4; m++) {
            int pi = m >> 1, hl = m & 1;
            float h2[4];
#pragma unroll
            for (int aa = 0; aa < 4; aa++) {
                float2 I = unpk(acc[pi][aa]);
                float2 F = unpk(acc[2 + pi][aa]);
                float2 G = unpk(acc[4 + pi][aa]);
                float2 O = unpk(acc[6 + pi][aa]);
                float iv = hl ? I.y : I.x, fv = hl ? F.y : F.x;
                float gv = hl ? G.y : G.x, ov = hl ? O.y : O.x;
                if (upd[aa]) {
                    float c2 = sigf(fv) * c[m][aa] + sigf(iv) * tanhf(gv);
                    c[m][aa] = c2;
                    h2[aa] = sigf(ov) * tanhf(c2);
                } else {
                    const float* hp = (const float*)&dup[warp][aa >> 1][EMBED + lane + 32 * m];
                    h2[aa] = hp[(aa & 1) * 2];
                }
            }
            int kk = EMBED + lane + 32 * m;
            dup[warp][0][kk] = make_float4(h2[0], h2[0], h2[1], h2[1]);
            dup[warp][1][kk] = make_float4(h2[2], h2[2], h2[3], h2[3]);
        }
        __syncwarp();
    }
}

extern "C" void kernel_launch(void* const* d_in, const int* in_sizes, int n_in,
                              void* d_out, int out_size) {
    const float* img     = (const float*)d_in[0];
    const float* obs_pos = (const float*)d_in[1];
    const int*   hist    = (const int*)d_in[2];
    const float* obs_rel = (const float*)d_in[3];
    const float* h0      = (const float*)d_in[4];
    const float* W_ih    = (const float*)d_in[5];
    const float* W_hh    = (const float*)d_in[6];
    const float* b_ih    = (const float*)d_in[7];
    const float* b_hh    = (const float*)d_in[8];
    const float* embed_W = (const float*)d_in[9];
    const float* embed_b = (const float*)d_in[10];
    const float* pred_W  = (const float*)d_in[11];
    const float* pred_b  = (const float*)d_in[12];
    float* out = (float*)d_out;

    cudaFuncSetAttribute(lstm_main, cudaFuncAttributeMaxDynamicSharedMemorySize, SMEM_BYTES);
    prep_weights<<<(KDIM * GATES + 255) / 256, 256>>>(W_ih, W_hh, b_ih, b_hh);
    img_proj_kernel<<<NAGENTS / 8, 256>>>(img, pred_W);
    lstm_main<<<NAGENTS / 32, 256, SMEM_BYTES>>>(obs_pos, hist, obs_rel, h0,
                                                 embed_W, embed_b, pred_W, pred_b, out);
}

// round 4
// speedup vs baseline: 1.4982x; 1.1714x over previous
#include <cuda_runtime.h>

#define NAGENTS 8192
#define OBSLEN  20
#define PREDLEN 30
#define EMBED   64
#define HIDDEN  128
#define CNNOUT  2048
#define GATES   512   /* 4*HIDDEN */
#define KDIM    192   /* EMBED + HIDDEN */

// Weight layout: float4 g_Wv[(k*4 + mm)*32 + lane] = (i,f,g,o) weights of
// hidden unit u = mm*32+lane at input k.  (j = e*128 + mm*32 + lane)
__device__ float4 g_Wv[(KDIM + 1) * 4 * 32];
__device__ float g_bias[GATES];
__device__ float g_imgproj[NAGENTS * 2];

// ---------------------------------------------------------------------------
// Combined prep: blocks [0,1024) do img projection; [1024,1408) do weights.
// ---------------------------------------------------------------------------
__global__ void prep_all(const float* __restrict__ img,
                         const float* __restrict__ pred_W,
                         const float* __restrict__ W_ih,
                         const float* __restrict__ W_hh,
                         const float* __restrict__ b_ih,
                         const float* __restrict__ b_hh) {
    int bid = blockIdx.x;
    if (bid < 1024) {
        int warp = threadIdx.x >> 5, lane = threadIdx.x & 31;
        int n = bid * 8 + warp;
        const float4* ip = (const float4*)(img + (size_t)n * CNNOUT);
        const float4* w0 = (const float4*)(pred_W + HIDDEN);
        const float4* w1 = (const float4*)(pred_W + (HIDDEN + CNNOUT) + HIDDEN);
        float s0 = 0.f, s1 = 0.f;
        for (int i = lane; i < CNNOUT / 4; i += 32) {
            float4 v = ip[i], a = w0[i], b = w1[i];
            s0 += v.x * a.x + v.y * a.y + v.z * a.z + v.w * a.w;
            s1 += v.x * b.x + v.y * b.y + v.z * b.z + v.w * b.w;
        }
#pragma unroll
        for (int o = 16; o; o >>= 1) {
            s0 += __shfl_xor_sync(0xFFFFFFFFu, s0, o);
            s1 += __shfl_xor_sync(0xFFFFFFFFu, s1, o);
        }
        if (lane == 0) { g_imgproj[n * 2] = s0; g_imgproj[n * 2 + 1] = s1; }
    } else {
        int idx = (bid - 1024) * 256 + threadIdx.x;
        if (idx < KDIM * GATES) {
            int k = idx / GATES, j = idx % GATES;
            int e = j >> 7, mm = (j >> 5) & 3, lane = j & 31;
            float v = (k < EMBED) ? W_ih[j * EMBED + k] : W_hh[j * HIDDEN + (k - EMBED)];
            ((float*)g_Wv)[(((k * 4 + mm) * 32 + lane) << 2) + e] = v;
        }
        if (idx < GATES) g_bias[idx] = b_ih[idx] + b_hh[idx];
    }
}

__device__ __forceinline__ float sigf(float x) { return 1.f / (1.f + __expf(-x)); }

__device__ __forceinline__ unsigned long long pack2(float lo, float hi) {
    unsigned long long r;
    asm("mov.b64 %0, {%1, %2};" : "=l"(r) : "f"(lo), "f"(hi));
    return r;
}
__device__ __forceinline__ float2 unpk(unsigned long long v) {
    float2 r;
    asm("mov.b64 {%0, %1}, %2;" : "=f"(r.x), "=f"(r.y) : "l"(v));
    return r;
}
#define FF2(a, w, i) asm("fma.rn.f32x2 %0, %1, %2, %0;" : "+l"(a) : "l"(w), "l"(i))
#define BARW(id) asm volatile("bar.sync %0, 64;" :: "r"(id) : "memory")

// ---------------------------------------------------------------------------
// 256 threads = 8 warps = 4 warp-pairs; 8 agents per pair, 32 per block.
// Warp (2g+half) handles hidden units half*64 .. half*64+63 of group g.
// f32x2 accumulators pair AGENTS; weights duplicated in-register (mov.b64).
// ---------------------------------------------------------------------------
__global__ __launch_bounds__(256, 2) void lstm_main(
    const float* __restrict__ obs_pos, const int* __restrict__ hist,
    const float* __restrict__ obs_rel, const float* __restrict__ h0,
    const float* __restrict__ embed_W, const float* __restrict__ embed_b,
    const float* __restrict__ pred_W,  const float* __restrict__ pred_b,
    float* __restrict__ out) {
    __shared__ ulonglong2 in_g[4][KDIM][2];       // [group][k][2]: 8 agents as 4 (a,a+1) pairs
    __shared__ unsigned long long b2_s[4][32][4]; // [mm][lane][e] = (b_j, b_j)
    __shared__ float ew0[EMBED], ew1[EMBED], eb[EMBED];
    __shared__ float pw[2][HIDDEN];
    __shared__ float src_s[4][8][2];
    __shared__ float pos_s[4][8][2];
    __shared__ float imgp_s[4][8][2];
    __shared__ int   hist_s[32];

    int tid = threadIdx.x, warp = tid >> 5, lane = tid & 31;
    int g = warp >> 1, half = warp & 1;
    int ab = blockIdx.x * 32;          // block agent base
    int a0 = g * 8;                    // group agent base (block-local)
    int barid = g + 1;

    // ---------------- init ----------------
    for (int i = tid; i < GATES; i += 256) {
        int mm = i >> 7, ln = (i >> 2) & 31, e = i & 3;
        float b = g_bias[e * 128 + mm * 32 + ln];
        b2_s[mm][ln][e] = pack2(b, b);
    }
    if (tid < EMBED) {
        ew0[tid] = embed_W[tid * 2];
        ew1[tid] = embed_W[tid * 2 + 1];
        eb[tid]  = embed_b[tid];
    }
    for (int i = tid; i < 2 * HIDDEN; i += 256)
        pw[i >> 7][i & 127] = pred_W[(i >> 7) * (HIDDEN + CNNOUT) + (i & 127)];
    if (tid < 32) hist_s[tid] = hist[ab + tid];
    if (tid < 64) {
        int a = tid >> 1, d = tid & 1;
        pos_s[a >> 3][a & 7][d]  = obs_pos[(size_t)(ab + a) * OBSLEN * 2 + (OBSLEN - 1) * 2 + d];
        imgp_s[a >> 3][a & 7][d] = g_imgproj[(ab + a) * 2 + d];
    }
    for (int i = tid; i < 4 * KDIM * 2; i += 256) {  // h0 / zero init of in_g
        int gg = i / (KDIM * 2), r = i % (KDIM * 2);
        int k = r >> 1, p2 = r & 1;
        float v = (k < EMBED) ? 0.f : h0[k - EMBED];
        unsigned long long pv = pack2(v, v);
        in_g[gg][k][p2] = make_ulonglong2(pv, pv);
    }
    float c[2][8];
#pragma unroll
    for (int m = 0; m < 2; m++) {
        float hv = h0[(half * 2 + m) * 32 + lane];
#pragma unroll
        for (int a = 0; a < 8; a++) c[m][a] = hv;
    }
    float pbd = pred_b[(lane >> 2) & 1];
    __syncthreads();

    int maxh8 = hist_s[a0];
#pragma unroll
    for (int a = 1; a < 8; a++) maxh8 = max(maxh8, hist_s[a0 + a]);

    // ---------------- 49 sequential steps ----------------
    for (int step = 0; step < OBSLEN - 1 + PREDLEN; step++) {
        bool obsPhase = step < OBSLEN - 1;
        int t = obsPhase ? (step + 1) : (step - (OBSLEN - 1));

        if (obsPhase) {
            if (maxh8 <= OBSLEN - t) continue;   // whole warp-pair masked
            if (half == 0 && lane < 16) {
                int a = lane >> 1, d = lane & 1;
                src_s[g][a][d] = obs_rel[(size_t)(ab + a0 + a) * OBSLEN * 2 + t * 2 + d];
            }
            BARW(barid);
        } else {
            // disp = h @ pred_W[:, :128].T + img_proj + pred_b; 16 tasks / 64 threads
            int task = lane >> 2, sub = lane & 3;
            int a = half * 4 + (task >> 1), d = task & 1;
            const float* inf = (const float*)in_g[g];
            float s = 0.f;
#pragma unroll 8
            for (int kk = 0; kk < 32; kk++) {
                int k = sub * 32 + kk;
                s = fmaf(pw[d][k], inf[(EMBED + k) * 8 + a], s);
            }
            s += __shfl_xor_sync(0xFFFFFFFFu, s, 1);
            s += __shfl_xor_sync(0xFFFFFFFFu, s, 2);
            if (sub == 0) {
                s += imgp_s[g][a][d] + pbd;
                float p = pos_s[g][a][d] + s;
                pos_s[g][a][d] = p;
                out[(size_t)(ab + a0 + a) * PREDLEN * 2 + t * 2 + d] = p;
                src_s[g][a][d] = s;
            }
            BARW(barid);
        }

        // embed: warp A writes rows 0..31, warp B rows 32..63
        {
            int k = half * 32 + lane;
            float w0 = ew0[k], w1 = ew1[k], bb = eb[k];
            float x[8];
#pragma unroll
            for (int a = 0; a < 8; a++)
                x[a] = fmaxf(fmaf(w0, src_s[g][a][0], fmaf(w1, src_s[g][a][1], bb)), 0.f);
            in_g[g][k][0] = make_ulonglong2(pack2(x[0], x[1]), pack2(x[2], x[3]));
            in_g[g][k][1] = make_ulonglong2(pack2(x[4], x[5]), pack2(x[6], x[7]));
        }
        BARW(barid);

        // ---- gate GEMM: acc[m][e][p], f32x2 over agent pairs ----
        unsigned long long acc[2][4][4];
#pragma unroll
        for (int m = 0; m < 2; m++)
#pragma unroll
            for (int e = 0; e < 4; e++) {
                unsigned long long b = b2_s[half * 2 + m][lane][e];
                acc[m][e][0] = b; acc[m][e][1] = b; acc[m][e][2] = b; acc[m][e][3] = b;
            }
        const float4* wp = g_Wv + (half * 2) * 32 + lane;
        const ulonglong2* inp = (const ulonglong2*)in_g[g];
        float4 wA = wp[0], wB = wp[32];
#pragma unroll 1
        for (int k = 0; k < KDIM; k++) {
            const float4* np = wp + 128;
            float4 nA = np[0], nB = np[32];
            ulonglong2 i01 = inp[2 * k], i23 = inp[2 * k + 1];
            unsigned long long w;
#define FMA4(m, e, wf) w = pack2(wf, wf); \
            FF2(acc[m][e][0], w, i01.x); FF2(acc[m][e][1], w, i01.y); \
            FF2(acc[m][e][2], w, i23.x); FF2(acc[m][e][3], w, i23.y)
            FMA4(0, 0, wA.x); FMA4(0, 1, wA.y); FMA4(0, 2, wA.z); FMA4(0, 3, wA.w);
            FMA4(1, 0, wB.x); FMA4(1, 1, wB.y); FMA4(1, 2, wB.z); FMA4(1, 3, wB.w);
#undef FMA4
            wA = nA; wB = nB; wp = np;
        }

        // ---- cell update; h written back as agent pairs ----
        bool upd[8];
#pragma unroll
        for (int a = 0; a < 8; a++)
            upd[a] = !obsPhase || (hist_s[a0 + a] > OBSLEN - t);
#pragma unroll
        for (int m = 0; m < 2; m++) {
            int row = EMBED + (half * 2 + m) * 32 + lane;
            float oldh[8];
            if (obsPhase) {
                ulonglong2 o01 = in_g[g][row][0], o23 = in_g[g][row][1];
                float2 f0 = unpk(o01.x), f1 = unpk(o01.y), f2 = unpk(o23.x), f3 = unpk(o23.y);
                oldh[0] = f0.x; oldh[1] = f0.y; oldh[2] = f1.x; oldh[3] = f1.y;
                oldh[4] = f2.x; oldh[5] = f2.y; oldh[6] = f3.x; oldh[7] = f3.y;
            }
            float h2[8];
#pragma unroll
            for (int p = 0; p < 4; p++) {
                float2 I = unpk(acc[m][0][p]);
                float2 F = unpk(acc[m][1][p]);
                float2 G = unpk(acc[m][2][p]);
                float2 O = unpk(acc[m][3][p]);
#pragma unroll
                for (int q = 0; q < 2; q++) {
                    int a = 2 * p + q;
                    float iv = q ? I.y : I.x, fv = q ? F.y : F.x;
                    float gv = q ? G.y : G.x, ov = q ? O.y : O.x;
                    if (upd[a]) {
                        float c2 = sigf(fv) * c[m][a] + sigf(iv) * tanhf(gv);
                        c[m][a] = c2;
                        h2[a] = sigf(ov) * tanhf(c2);
                    } else {
                        h2[a] = oldh[a];
                    }
                }
            }
            in_g[g][row][0] = make_ulonglong2(pack2(h2[0], h2[1]), pack2(h2[2], h2[3]));
            in_g[g][row][1] = make_ulonglong2(pack2(h2[4], h2[5]), pack2(h2[6], h2[7]));
        }
        BARW(barid);   // h visible to partner warp before next disp/GEMM
    }
}

extern "C" void kernel_launch(void* const* d_in, const int* in_sizes, int n_in,
                              void* d_out, int out_size) {
    const float* img     = (const float*)d_in[0];
    const float* obs_pos = (const float*)d_in[1];
    const int*   hist    = (const int*)d_in[2];
    const float* obs_rel = (const float*)d_in[3];
    const float* h0      = (const float*)d_in[4];
    const float* W_ih    = (const float*)d_in[5];
    const float* W_hh    = (const float*)d_in[6];
    const float* b_ih    = (const float*)d_in[7];
    const float* b_hh    = (const float*)d_in[8];
    const float* embed_W = (const float*)d_in[9];
    const float* embed_b = (const float*)d_in[10];
    const float* pred_W  = (const float*)d_in[11];
    const float* pred_b  = (const float*)d_in[12];
    float* out = (float*)d_out;

    prep_all<<<1024 + 384, 256>>>(img, pred_W, W_ih, W_hh, b_ih, b_hh);
    lstm_main<<<NAGENTS / 32, 256>>>(obs_pos, hist, obs_rel, h0,
                                     embed_W, embed_b, pred_W, pred_b, out);
}

// round 5
// speedup vs baseline: 1.4995x; 1.0009x over previous
#include <cuda_runtime.h>

#define NAGENTS 8192
#define OBSLEN  20
#define PREDLEN 30
#define EMBED   64
#define HIDDEN  128
#define CNNOUT  2048
#define GATES   512   /* 4*HIDDEN */
#define KDIM    192   /* EMBED + HIDDEN */

// Weight layout: float4 g_Wv[(k*4 + mm)*32 + lane] = (i,f,g,o) weights of
// hidden unit u = mm*32+lane at input k.  (j = e*128 + mm*32 + lane)
__device__ float4 g_Wv[(KDIM + 1) * 4 * 32];
__device__ float g_bias[GATES];
__device__ float g_imgproj[NAGENTS * 2];

// ---------------------------------------------------------------------------
// Combined prep: blocks [0,1024) do img projection; [1024,1408) do weights.
// ---------------------------------------------------------------------------
__global__ void prep_all(const float* __restrict__ img,
                         const float* __restrict__ pred_W,
                         const float* __restrict__ W_ih,
                         const float* __restrict__ W_hh,
                         const float* __restrict__ b_ih,
                         const float* __restrict__ b_hh) {
    int bid = blockIdx.x;
    if (bid < 1024) {
        int warp = threadIdx.x >> 5, lane = threadIdx.x & 31;
        int n = bid * 8 + warp;
        const float4* ip = (const float4*)(img + (size_t)n * CNNOUT);
        const float4* w0 = (const float4*)(pred_W + HIDDEN);
        const float4* w1 = (const float4*)(pred_W + (HIDDEN + CNNOUT) + HIDDEN);
        float s0 = 0.f, s1 = 0.f;
        for (int i = lane; i < CNNOUT / 4; i += 32) {
            float4 v = ip[i], a = w0[i], b = w1[i];
            s0 += v.x * a.x + v.y * a.y + v.z * a.z + v.w * a.w;
            s1 += v.x * b.x + v.y * b.y + v.z * b.z + v.w * b.w;
        }
#pragma unroll
        for (int o = 16; o; o >>= 1) {
            s0 += __shfl_xor_sync(0xFFFFFFFFu, s0, o);
            s1 += __shfl_xor_sync(0xFFFFFFFFu, s1, o);
        }
        if (lane == 0) { g_imgproj[n * 2] = s0; g_imgproj[n * 2 + 1] = s1; }
    } else {
        int idx = (bid - 1024) * 256 + threadIdx.x;
        if (idx < KDIM * GATES) {
            int k = idx / GATES, j = idx % GATES;
            int e = j >> 7, mm = (j >> 5) & 3, lane = j & 31;
            float v = (k < EMBED) ? W_ih[j * EMBED + k] : W_hh[j * HIDDEN + (k - EMBED)];
            ((float*)g_Wv)[(((k * 4 + mm) * 32 + lane) << 2) + e] = v;
        }
        if (idx < GATES) g_bias[idx] = b_ih[idx] + b_hh[idx];
    }
}

__device__ __forceinline__ float sigf(float x) { return 1.f / (1.f + __expf(-x)); }

__device__ __forceinline__ unsigned long long pack2(float lo, float hi) {
    unsigned long long r;
    asm("mov.b64 %0, {%1, %2};" : "=l"(r) : "f"(lo), "f"(hi));
    return r;
}
__device__ __forceinline__ float2 unpk(unsigned long long v) {
    float2 r;
    asm("mov.b64 {%0, %1}, %2;" : "=f"(r.x), "=f"(r.y) : "l"(v));
    return r;
}
#define FF2(a, w, i) asm("fma.rn.f32x2 %0, %1, %2, %0;" : "+l"(a) : "l"(w), "l"(i))
#define BARW(id) asm volatile("bar.sync %0, 64;" :: "r"(id) : "memory")

// ---------------------------------------------------------------------------
// 256 threads = 8 warps = 4 warp-pairs; 8 agents per pair, 32 per block.
// Warp (2g+half) handles hidden units half*64 .. half*64+63 of group g.
// f32x2 accumulators pair AGENTS; weights duplicated in-register (mov.b64).
// ---------------------------------------------------------------------------
__global__ __launch_bounds__(256, 2) void lstm_main(
    const float* __restrict__ obs_pos, const int* __restrict__ hist,
    const float* __restrict__ obs_rel, const float* __restrict__ h0,
    const float* __restrict__ embed_W, const float* __restrict__ embed_b,
    const float* __restrict__ pred_W,  const float* __restrict__ pred_b,
    float* __restrict__ out) {
    __shared__ ulonglong2 in_g[4][KDIM][2];       // [group][k][2]: 8 agents as 4 (a,a+1) pairs
    __shared__ unsigned long long b2_s[4][32][4]; // [mm][lane][e] = (b_j, b_j)
    __shared__ float ew0[EMBED], ew1[EMBED], eb[EMBED];
    __shared__ float pw[2][HIDDEN];
    __shared__ float src_s[4][8][2];
    __shared__ float pos_s[4][8][2];
    __shared__ float imgp_s[4][8][2];
    __shared__ int   hist_s[32];

    int tid = threadIdx.x, warp = tid >> 5, lane = tid & 31;
    int g = warp >> 1, half = warp & 1;
    int ab = blockIdx.x * 32;          // block agent base
    int a0 = g * 8;                    // group agent base (block-local)
    int barid = g + 1;

    // ---------------- init ----------------
    for (int i = tid; i < GATES; i += 256) {
        int mm = i >> 7, ln = (i >> 2) & 31, e = i & 3;
        float b = g_bias[e * 128 + mm * 32 + ln];
        b2_s[mm][ln][e] = pack2(b, b);
    }
    if (tid < EMBED) {
        ew0[tid] = embed_W[tid * 2];
        ew1[tid] = embed_W[tid * 2 + 1];
        eb[tid]  = embed_b[tid];
    }
    for (int i = tid; i < 2 * HIDDEN; i += 256)
        pw[i >> 7][i & 127] = pred_W[(i >> 7) * (HIDDEN + CNNOUT) + (i & 127)];
    if (tid < 32) hist_s[tid] = hist[ab + tid];
    if (tid < 64) {
        int a = tid >> 1, d = tid & 1;
        pos_s[a >> 3][a & 7][d]  = obs_pos[(size_t)(ab + a) * OBSLEN * 2 + (OBSLEN - 1) * 2 + d];
        imgp_s[a >> 3][a & 7][d] = g_imgproj[(ab + a) * 2 + d];
    }
    for (int i = tid; i < 4 * KDIM * 2; i += 256) {  // h0 / zero init of in_g
        int gg = i / (KDIM * 2), r = i % (KDIM * 2);
        int k = r >> 1, p2 = r & 1;
        float v = (k < EMBED) ? 0.f : h0[k - EMBED];
        unsigned long long pv = pack2(v, v);
        in_g[gg][k][p2] = make_ulonglong2(pv, pv);
    }
    float c[2][8];
#pragma unroll
    for (int m = 0; m < 2; m++) {
        float hv = h0[(half * 2 + m) * 32 + lane];
#pragma unroll
        for (int a = 0; a < 8; a++) c[m][a] = hv;
    }
    float pbd = pred_b[(lane >> 2) & 1];
    __syncthreads();

    int maxh8 = hist_s[a0];
#pragma unroll
    for (int a = 1; a < 8; a++) maxh8 = max(maxh8, hist_s[a0 + a]);

    // ---------------- 49 sequential steps ----------------
    for (int step = 0; step < OBSLEN - 1 + PREDLEN; step++) {
        bool obsPhase = step < OBSLEN - 1;
        int t = obsPhase ? (step + 1) : (step - (OBSLEN - 1));

        if (obsPhase) {
            if (maxh8 <= OBSLEN - t) continue;   // whole warp-pair masked
            if (half == 0 && lane < 16) {
                int a = lane >> 1, d = lane & 1;
                src_s[g][a][d] = obs_rel[(size_t)(ab + a0 + a) * OBSLEN * 2 + t * 2 + d];
            }
            BARW(barid);
        } else {
            // disp = h @ pred_W[:, :128].T + img_proj + pred_b; 16 tasks / 64 threads
            int task = lane >> 2, sub = lane & 3;
            int a = half * 4 + (task >> 1), d = task & 1;
            const float* inf = (const float*)in_g[g];
            float s = 0.f;
#pragma unroll 8
            for (int kk = 0; kk < 32; kk++) {
                int k = sub * 32 + kk;
                s = fmaf(pw[d][k], inf[(EMBED + k) * 8 + a], s);
            }
            s += __shfl_xor_sync(0xFFFFFFFFu, s, 1);
            s += __shfl_xor_sync(0xFFFFFFFFu, s, 2);
            if (sub == 0) {
                s += imgp_s[g][a][d] + pbd;
                float p = pos_s[g][a][d] + s;
                pos_s[g][a][d] = p;
                out[(size_t)(ab + a0 + a) * PREDLEN * 2 + t * 2 + d] = p;
                src_s[g][a][d] = s;
            }
            BARW(barid);
        }

        // embed: warp A writes rows 0..31, warp B rows 32..63
        {
            int k = half * 32 + lane;
            float w0 = ew0[k], w1 = ew1[k], bb = eb[k];
            float x[8];
#pragma unroll
            for (int a = 0; a < 8; a++)
                x[a] = fmaxf(fmaf(w0, src_s[g][a][0], fmaf(w1, src_s[g][a][1], bb)), 0.f);
            in_g[g][k][0] = make_ulonglong2(pack2(x[0], x[1]), pack2(x[2], x[3]));
            in_g[g][k][1] = make_ulonglong2(pack2(x[4], x[5]), pack2(x[6], x[7]));
        }
        BARW(barid);

        // ---- gate GEMM: acc[m][e][p], f32x2 over agent pairs ----
        unsigned long long acc[2][4][4];
#pragma unroll
        for (int m = 0; m < 2; m++)
#pragma unroll
            for (int e = 0; e < 4; e++) {
                unsigned long long b = b2_s[half * 2 + m][lane][e];
                acc[m][e][0] = b; acc[m][e][1] = b; acc[m][e][2] = b; acc[m][e][3] = b;
            }
        const float4* wp = g_Wv + (half * 2) * 32 + lane;
        const ulonglong2* inp = (const ulonglong2*)in_g[g];
        float4 wA = wp[0], wB = wp[32];
#pragma unroll 1
        for (int k = 0; k < KDIM; k++) {
            const float4* np = wp + 128;
            float4 nA = np[0], nB = np[32];
            ulonglong2 i01 = inp[2 * k], i23 = inp[2 * k + 1];
            unsigned long long w;
#define FMA4(m, e, wf) w = pack2(wf, wf); \
            FF2(acc[m][e][0], w, i01.x); FF2(acc[m][e][1], w, i01.y); \
            FF2(acc[m][e][2], w, i23.x); FF2(acc[m][e][3], w, i23.y)
            FMA4(0, 0, wA.x); FMA4(0, 1, wA.y); FMA4(0, 2, wA.z); FMA4(0, 3, wA.w);
            FMA4(1, 0, wB.x); FMA4(1, 1, wB.y); FMA4(1, 2, wB.z); FMA4(1, 3, wB.w);
#undef FMA4
            wA = nA; wB = nB; wp = np;
        }

        // ---- cell update; h written back as agent pairs ----
        bool upd[8];
#pragma unroll
        for (int a = 0; a < 8; a++)
            upd[a] = !obsPhase || (hist_s[a0 + a] > OBSLEN - t);
#pragma unroll
        for (int m = 0; m < 2; m++) {
            int row = EMBED + (half * 2 + m) * 32 + lane;
            float oldh[8];
            if (obsPhase) {
                ulonglong2 o01 = in_g[g][row][0], o23 = in_g[g][row][1];
                float2 f0 = unpk(o01.x), f1 = unpk(o01.y), f2 = unpk(o23.x), f3 = unpk(o23.y);
                oldh[0] = f0.x; oldh[1] = f0.y; oldh[2] = f1.x; oldh[3] = f1.y;
                oldh[4] = f2.x; oldh[5] = f2.y; oldh[6] = f3.x; oldh[7] = f3.y;
            }
            float h2[8];
#pragma unroll
            for (int p = 0; p < 4; p++) {
                float2 I = unpk(acc[m][0][p]);
                float2 F = unpk(acc[m][1][p]);
                float2 G = unpk(acc[m][2][p]);
                float2 O = unpk(acc[m][3][p]);
#pragma unroll
                for (int q = 0; q < 2; q++) {
                    int a = 2 * p + q;
                    float iv = q ? I.y : I.x, fv = q ? F.y : F.x;
                    float gv = q ? G.y : G.x, ov = q ? O.y : O.x;
                    if (upd[a]) {
                        float c2 = sigf(fv) * c[m][a] + sigf(iv) * tanhf(gv);
                        c[m][a] = c2;
                        h2[a] = sigf(ov) * tanhf(c2);
                    } else {
                        h2[a] = oldh[a];
                    }
                }
            }
            in_g[g][row][0] = make_ulonglong2(pack2(h2[0], h2[1]), pack2(h2[2], h2[3]));
            in_g[g][row][1] = make_ulonglong2(pack2(h2[4], h2[5]), pack2(h2[6], h2[7]));
        }
        BARW(barid);   // h visible to partner warp before next disp/GEMM
    }
}

extern "C" void kernel_launch(void* const* d_in, const int* in_sizes, int n_in,
                              void* d_out, int out_size) {
    const float* img     = (const float*)d_in[0];
    const float* obs_pos = (const float*)d_in[1];
    const int*   hist    = (const int*)d_in[2];
    const float* obs_rel = (const float*)d_in[3];
    const float* h0      = (const float*)d_in[4];
    const float* W_ih    = (const float*)d_in[5];
    const float* W_hh    = (const float*)d_in[6];
    const float* b_ih    = (const float*)d_in[7];
    const float* b_hh    = (const float*)d_in[8];
    const float* embed_W = (const float*)d_in[9];
    const float* embed_b = (const float*)d_in[10];
    const float* pred_W  = (const float*)d_in[11];
    const float* pred_b  = (const float*)d_in[12];
    float* out = (float*)d_out;

    prep_all<<<1024 + 384, 256>>>(img, pred_W, W_ih, W_hh, b_ih, b_hh);
    lstm_main<<<NAGENTS / 32, 256>>>(obs_pos, hist, obs_rel, h0,
                                     embed_W, embed_b, pred_W, pred_b, out);
}